// round 6
// baseline (speedup 1.0000x reference)
#include <cuda_runtime.h>
#include <cstdint>

#define FULLMASK 0xffffffffu

// Problem constants (fixed dataset)
constexpr int NNODES = 100000;
constexpr int NEDGES = 1000000;
constexpr int HDIM   = 64;
constexpr int ODIM   = 16;
constexpr int RNUM   = 90;
constexpr int BNUM   = 8;

constexpr int TE      = 512;   // edges per tile (one relation per tile)
constexpr int EWARPS  = 4;     // warps per edge-block
constexpr int EBATCH  = 8;     // edges per warp per pass (edge16 kernel)
constexpr int SBLOCKS = 512;   // blocks for hist/scatter
constexpr int MAX_TILES = NEDGES / TE + RNUM + 8;

// ---------------- scratch (device globals; no allocation) ----------------
__device__ float g_h0[(size_t)NNODES * HDIM];
__device__ float g_h1[(size_t)NNODES * HDIM];
__device__ float g_Wp[RNUM * HDIM * HDIM];   // packed per-relation weights (reused per layer)
__device__ int   g_hist[RNUM];
__device__ int   g_bh[SBLOCKS * RNUM];       // per-block relation histograms
__device__ int   g_bo[SBLOCKS * RNUM];       // per-block scatter offsets
__device__ int4  g_tiles[MAX_TILES];         // {rel, start, len, 0}
__device__ int   g_numTiles;
__device__ int4  g_edges[NEDGES];            // {src, dst, bits(norm), 0} sorted by relation

// ---------------- f32x2 helpers ----------------
__device__ __forceinline__ unsigned long long pack2(float lo, float hi) {
    unsigned long long r;
    asm("mov.b64 %0, {%1, %2};" : "=l"(r) : "f"(lo), "f"(hi));
    return r;
}
__device__ __forceinline__ float2 unpack2(unsigned long long v) {
    float2 f;
    asm("mov.b64 {%0, %1}, %2;" : "=f"(f.x), "=f"(f.y) : "l"(v));
    return f;
}
__device__ __forceinline__ unsigned long long fma2(unsigned long long a,
                                                   unsigned long long b,
                                                   unsigned long long c) {
    unsigned long long d;
    asm("fma.rn.f32x2 %0, %1, %2, %3;" : "=l"(d) : "l"(a), "l"(b), "l"(c));
    return d;
}
__device__ __forceinline__ unsigned long long add2(unsigned long long a,
                                                   unsigned long long b) {
    unsigned long long d;
    asm("add.rn.f32x2 %0, %1, %2;" : "=l"(d) : "l"(a), "l"(b));
    return d;
}

// ---------------- hierarchical counting sort by relation ----------------
__global__ void k_hist(const int* __restrict__ et, int E) {
    __shared__ int h[RNUM];
    for (int i = threadIdx.x; i < RNUM; i += blockDim.x) h[i] = 0;
    __syncthreads();
    int chunk = (E + SBLOCKS - 1) / SBLOCKS;
    int lo = blockIdx.x * chunk;
    int hi = min(E, lo + chunk);
    for (int e = lo + threadIdx.x; e < hi; e += blockDim.x)
        atomicAdd(&h[et[e]], 1);
    __syncthreads();
    for (int i = threadIdx.x; i < RNUM; i += blockDim.x)
        g_bh[blockIdx.x * RNUM + i] = h[i];
}

// Single block: per-relation scan over block hists, tile list, global offsets.
__global__ void k_offsets() {
    __shared__ int relStart[RNUM];
    int r = threadIdx.x;
    if (r < RNUM) {
        int running = 0;
        for (int blk = 0; blk < SBLOCKS; blk++) {
            g_bo[blk * RNUM + r] = running;
            running += g_bh[blk * RNUM + r];
        }
        g_hist[r] = running;   // per-relation count
    }
    __syncthreads();
    if (threadIdx.x == 0) {
        int running = 0, n = 0;
        for (int rr = 0; rr < RNUM; rr++) {
            relStart[rr] = running;
            int c = g_hist[rr];
            int t = 0;
            while (t < c) {
                int len = (c - t < TE) ? (c - t) : TE;
                g_tiles[n] = make_int4(rr, running + t, len, 0);
                n++;
                t += TE;
            }
            running += c;
        }
        g_numTiles = n;
    }
    __syncthreads();
    if (r < RNUM) {
        int rs = relStart[r];
        for (int blk = 0; blk < SBLOCKS; blk++)
            g_bo[blk * RNUM + r] += rs;
    }
}

__global__ void k_scatter(const int* __restrict__ src, const int* __restrict__ dst,
                          const int* __restrict__ et, const float* __restrict__ norm, int E) {
    __shared__ int cur[RNUM];
    for (int i = threadIdx.x; i < RNUM; i += blockDim.x)
        cur[i] = g_bo[blockIdx.x * RNUM + i];
    __syncthreads();
    int chunk = (E + SBLOCKS - 1) / SBLOCKS;
    int lo = blockIdx.x * chunk;
    int hi = min(E, lo + chunk);
    for (int e = lo + threadIdx.x; e < hi; e += blockDim.x) {
        int r = et[e];
        int p = atomicAdd(&cur[r], 1);
        g_edges[p] = make_int4(src[e], dst[e], __float_as_int(norm[e]), 0);
    }
}

// ---------------- weight packing ----------------
// Layer 64->64: row-PAIR packed: float idx = r*4096 + kp*128 + c*2 + rr
// i.e. float2 entry [kp*64 + c] = { W[2kp][c], W[2kp+1][c] }  (k-vectorized fma2)
__global__ void k_packW64(const float* __restrict__ coeff, const float* __restrict__ bases) {
    int idx = blockIdx.x * blockDim.x + threadIdx.x;
    if (idx >= RNUM * 4096) return;
    int r   = idx >> 12;
    int rem = idx & 4095;
    int kp  = rem >> 7;
    int c   = (rem >> 1) & 63;
    int rr  = rem & 1;
    int row = 2 * kp + rr;
    float v = 0.f;
#pragma unroll
    for (int b = 0; b < BNUM; b++)
        v += coeff[r * BNUM + b] * bases[(b * HDIM + row) * HDIM + c];
    g_Wp[idx] = v;
}

// Layer 64->16: float layout idx = r*1024 + rp*32 + j*2 + rr
// entry(8B) [rp*16+j] = { W[2rp][j], W[2rp+1][j] }
__global__ void k_packW16(const float* __restrict__ coeff, const float* __restrict__ bases) {
    int idx = blockIdx.x * blockDim.x + threadIdx.x;
    if (idx >= RNUM * 1024) return;
    int r   = idx >> 10;
    int rem = idx & 1023;
    int rp  = rem >> 5;
    int j   = (rem >> 1) & 15;
    int rr  = rem & 1;
    int row = 2 * rp + rr;
    float v = 0.f;
#pragma unroll
    for (int b = 0; b < BNUM; b++)
        v += coeff[r * BNUM + b] * bases[(b * HDIM + row) * ODIM + j];
    g_Wp[idx] = v;
}

__global__ void k_init(float* __restrict__ h, const float* __restrict__ bias,
                       int total, int mask) {
    int i = blockIdx.x * blockDim.x + threadIdx.x;
    if (i < total) h[i] = bias[i & mask];
}

// ---------------- edge kernel, 64 output cols (register-W, shuffle-X) ---------
// One warp processes one edge at a time. Lane = (kh in {0,1}) * 16 + cq.
// Lane holds W[k-pairs kh*16..kh*16+15][cols 4cq..4cq+3] in 128 registers,
// pre-packed as row-pair float2s. X pairs are loaded coalesced (lane l =
// k-pair l) and broadcast via shuffles. No shared memory in the hot loop.
template <bool RELU>
__global__ void __launch_bounds__(128)
k_edge64(const float* __restrict__ x, float* __restrict__ hout) {
    int tb = blockIdx.x;
    if (tb >= g_numTiles) return;
    int4 tile = g_tiles[tb];
    int rel = tile.x, start = tile.y, len = tile.z;

    const int warp = threadIdx.x >> 5;
    const int lane = threadIdx.x & 31;
    const int kh   = lane >> 4;       // k-half (which 16 k-pairs)
    const int cq   = lane & 15;       // column quad (cols 4cq..4cq+3)
    const int kbase = kh * 16;

    // Load this lane's W block into registers (once per tile, L2-resident).
    ulonglong2 wA[16], wB[16];        // wA: col-pairs (c0,c1); wB: (c2,c3)
    {
        const float2* wp = (const float2*)(g_Wp + (size_t)rel * 4096);
#pragma unroll
        for (int t = 0; t < 16; t++) {
            const ulonglong2* p =
                (const ulonglong2*)(wp + ((kbase + t) * 64 + cq * 4));
            wA[t] = p[0];
            wB[t] = p[1];
        }
    }

    const float2* x2 = (const float2*)x;

    for (int base = warp * 32; base < len; base += 128) {
        int cnt = min(32, len - base);
        int4 md = make_int4(0, 0, 0, 0);
        if (lane < cnt) md = g_edges[start + base + lane];

        // software pipeline: x rows for edges e, e+1 in flight
        float2 xa, xb;
        {
            int s0 = __shfl_sync(FULLMASK, md.x, 0);
            xa = x2[(size_t)s0 * 32 + lane];
        }
        if (cnt > 1) {
            int s1 = __shfl_sync(FULLMASK, md.x, 1);
            xb = x2[(size_t)s1 * 32 + lane];
        } else {
            xb = xa;
        }

        for (int e = 0; e < cnt; e++) {
            float2 xc = xa;
            xa = xb;
            if (e + 2 < cnt) {
                int sn = __shfl_sync(FULLMASK, md.x, e + 2);
                xb = x2[(size_t)sn * 32 + lane];
            }
            float nm = __int_as_float(__shfl_sync(FULLMASK, md.z, e));
            if (RELU) { xc.x = fmaxf(xc.x, 0.f); xc.y = fmaxf(xc.y, 0.f); }
            unsigned long long xmine = pack2(xc.x * nm, xc.y * nm);

            unsigned long long a0 = 0ull, a1 = 0ull, a2 = 0ull, a3 = 0ull;
#pragma unroll
            for (int t = 0; t < 16; t++) {
                unsigned long long xk = __shfl_sync(FULLMASK, xmine, kbase + t);
                a0 = fma2(xk, wA[t].x, a0);
                a1 = fma2(xk, wA[t].y, a1);
                a2 = fma2(xk, wB[t].x, a2);
                a3 = fma2(xk, wB[t].y, a3);
            }
            // combine the two k-halves (partner lane = lane ^ 16)
            a0 = add2(a0, __shfl_xor_sync(FULLMASK, a0, 16));
            a1 = add2(a1, __shfl_xor_sync(FULLMASK, a1, 16));
            a2 = add2(a2, __shfl_xor_sync(FULLMASK, a2, 16));
            a3 = add2(a3, __shfl_xor_sync(FULLMASK, a3, 16));

            int d = __shfl_sync(FULLMASK, md.y, e);
            if (kh == 0) {
                float2 f0 = unpack2(a0), f1 = unpack2(a1);
                float2 f2 = unpack2(a2), f3 = unpack2(a3);
                atomicAdd((float4*)(hout + (size_t)d * 64 + cq * 4),
                          make_float4(f0.x + f0.y, f1.x + f1.y,
                                      f2.x + f2.y, f3.x + f3.y));
            }
        }
    }
}

// ---------------- edge kernel, 16 output cols (final layer) ----------------
// lane = half*16 + j : half splits the i-range (i in [32h, 32h+32)), lane owns col j.
__global__ void __launch_bounds__(EWARPS * 32)
k_edge16(const float* __restrict__ x, float* __restrict__ out) {
    __shared__ unsigned long long sW2[32 * 16];            // 4 KB
    __shared__ unsigned long long sX2[EWARPS][EBATCH][32]; // 8 KB (plain pairs)

    int tb = blockIdx.x;
    if (tb >= g_numTiles) return;
    int4 tile = g_tiles[tb];
    int rel = tile.x, start = tile.y, len = tile.z;

    {
        const unsigned long long* wg = (const unsigned long long*)(g_Wp + (size_t)rel * 1024);
        for (int i = threadIdx.x; i < 512; i += blockDim.x) sW2[i] = wg[i];
    }
    __syncthreads();

    const int warp = threadIdx.x >> 5;
    const int lane = threadIdx.x & 31;
    const int half = lane >> 4;
    const int j    = lane & 15;
    const float2* x2 = (const float2*)x;

    // hoist this lane's W column pairs into registers (shared across all edges)
    unsigned long long wr[16];
#pragma unroll
    for (int t = 0; t < 16; t++) wr[t] = sW2[(half * 16 + t) * 16 + j];

    for (int base = warp * EBATCH; base < len; base += EWARPS * EBATCH) {
        __syncwarp();
        int4 ed = make_int4(0, 0, 0, 0);
        if (lane < EBATCH && base + lane < len)
            ed = g_edges[start + base + lane];
        int s = ed.x, d = ed.y;
        float nm = __int_as_float(ed.z);

#pragma unroll
        for (int e = 0; e < EBATCH; e++) {
            int   ss = __shfl_sync(FULLMASK, s, e);
            float nn = __shfl_sync(FULLMASK, nm, e);
            float2 v = x2[(size_t)ss * 32 + lane];
            v.x = fmaxf(v.x, 0.f); v.y = fmaxf(v.y, 0.f);   // final layer always relu's input
            v.x *= nn; v.y *= nn;
            sX2[warp][e][lane] = pack2(v.x, v.y);
        }
        __syncwarp();

#pragma unroll
        for (int e = 0; e < EBATCH; e++) {
            unsigned long long acc = 0ull;
#pragma unroll
            for (int t = 0; t < 16; t++)
                acc = fma2(sX2[warp][e][half * 16 + t], wr[t], acc);
            float2 pr = unpack2(acc);
            float  rs = pr.x + pr.y;
            rs += __shfl_xor_sync(FULLMASK, rs, 16);      // combine the two i-halves
            float v1 = __shfl_down_sync(FULLMASK, rs, 1);
            float v2 = __shfl_down_sync(FULLMASK, rs, 2);
            float v3 = __shfl_down_sync(FULLMASK, rs, 3);
            int de = __shfl_sync(FULLMASK, d, e);
            if (half == 0 && (j & 3) == 0)
                atomicAdd((float4*)(out + (size_t)de * 16 + j),
                          make_float4(rs, v1, v2, v3));
        }
    }
}

// ---------------- launch ----------------
extern "C" void kernel_launch(void* const* d_in, const int* in_sizes, int n_in,
                              void* d_out, int out_size) {
    const float* feats  = (const float*)d_in[0];
    const float* coeff0 = (const float*)d_in[1];
    const float* bases0 = (const float*)d_in[2];
    const float* bias0  = (const float*)d_in[3];
    const float* coeff1 = (const float*)d_in[4];
    const float* bases1 = (const float*)d_in[5];
    const float* bias1  = (const float*)d_in[6];
    const float* coeff2 = (const float*)d_in[7];
    const float* bases2 = (const float*)d_in[8];
    const float* bias2  = (const float*)d_in[9];
    const int*   src    = (const int*)d_in[10];
    const int*   dst    = (const int*)d_in[11];
    const int*   etype  = (const int*)d_in[12];
    const float* norm   = (const float*)d_in[13];
    float* out = (float*)d_out;

    int E = in_sizes[10];
    if (E > NEDGES) E = NEDGES;
    int N = in_sizes[0] / HDIM;
    if (N > NNODES) N = NNODES;

    float* h0;  cudaGetSymbolAddress((void**)&h0, g_h0);
    float* h1;  cudaGetSymbolAddress((void**)&h1, g_h1);

    // ---- sort edges by relation (shared by all 3 layers) ----
    k_hist<<<SBLOCKS, 256>>>(etype, E);
    k_offsets<<<1, 128>>>();
    k_scatter<<<SBLOCKS, 256>>>(src, dst, etype, norm, E);

    int gridTiles = MAX_TILES;

    // ---- layer 0: feats -> h0 (relu applied by next layer's reader) ----
    k_packW64<<<(RNUM * 4096 + 255) / 256, 256>>>(coeff0, bases0);
    k_init<<<(N * HDIM + 255) / 256, 256>>>(h0, bias0, N * HDIM, HDIM - 1);
    k_edge64<false><<<gridTiles, 128>>>(feats, h0);

    // ---- layer 1: relu(h0) -> h1 ----
    k_packW64<<<(RNUM * 4096 + 255) / 256, 256>>>(coeff1, bases1);
    k_init<<<(N * HDIM + 255) / 256, 256>>>(h1, bias1, N * HDIM, HDIM - 1);
    k_edge64<true><<<gridTiles, 128>>>(h0, h1);

    // ---- layer 2: relu(h1) -> out ----
    k_packW16<<<(RNUM * 1024 + 255) / 256, 256>>>(coeff2, bases2);
    k_init<<<(N * ODIM + 255) / 256, 256>>>(out, bias2, N * ODIM, ODIM - 1);
    k_edge16<<<gridTiles, EWARPS * 32>>>(h1, out);
}

// round 7
// speedup vs baseline: 1.2674x; 1.2674x over previous
#include <cuda_runtime.h>
#include <cstdint>

#define FULLMASK 0xffffffffu

// Problem constants (fixed dataset)
constexpr int NNODES = 100000;
constexpr int NEDGES = 1000000;
constexpr int HDIM   = 64;
constexpr int ODIM   = 16;
constexpr int RNUM   = 90;
constexpr int BNUM   = 8;

constexpr int TE      = 512;   // edges per tile (one relation per tile)
constexpr int EWARPS  = 4;     // warps per edge-block
constexpr int EB64    = 16;    // edges per warp per pass (edge64 kernel)
constexpr int EBATCH  = 8;     // edges per warp per pass (edge16 kernel)
constexpr int SBLOCKS = 512;   // blocks for hist/scatter
constexpr int MAX_TILES = NEDGES / TE + RNUM + 8;

// ---------------- scratch (device globals; no allocation) ----------------
__device__ float g_h0[(size_t)NNODES * HDIM];
__device__ float g_h1[(size_t)NNODES * HDIM];
__device__ float g_Wp[RNUM * HDIM * HDIM];   // packed per-relation weights (reused per layer)
__device__ int   g_hist[RNUM];
__device__ int   g_bh[SBLOCKS * RNUM];       // per-block relation histograms
__device__ int   g_bo[SBLOCKS * RNUM];       // per-block scatter offsets
__device__ int4  g_tiles[MAX_TILES];         // {rel, start, len, 0}
__device__ int   g_numTiles;
__device__ int4  g_edges[NEDGES];            // {src, dst, bits(norm), 0} sorted by relation

// ---------------- f32x2 helpers ----------------
__device__ __forceinline__ unsigned long long pack2(float lo, float hi) {
    unsigned long long r;
    asm("mov.b64 %0, {%1, %2};" : "=l"(r) : "f"(lo), "f"(hi));
    return r;
}
__device__ __forceinline__ float2 unpack2(unsigned long long v) {
    float2 f;
    asm("mov.b64 {%0, %1}, %2;" : "=f"(f.x), "=f"(f.y) : "l"(v));
    return f;
}
__device__ __forceinline__ unsigned long long fma2(unsigned long long a,
                                                   unsigned long long b,
                                                   unsigned long long c) {
    unsigned long long d;
    asm("fma.rn.f32x2 %0, %1, %2, %3;" : "=l"(d) : "l"(a), "l"(b), "l"(c));
    return d;
}
__device__ __forceinline__ float fold2(unsigned long long a) {
    float2 f = unpack2(a);
    return f.x + f.y;
}

// ---------------- hierarchical counting sort by relation ----------------
__global__ void k_hist(const int* __restrict__ et, int E) {
    __shared__ int h[RNUM];
    for (int i = threadIdx.x; i < RNUM; i += blockDim.x) h[i] = 0;
    __syncthreads();
    int chunk = (E + SBLOCKS - 1) / SBLOCKS;
    int lo = blockIdx.x * chunk;
    int hi = min(E, lo + chunk);
    for (int e = lo + threadIdx.x; e < hi; e += blockDim.x)
        atomicAdd(&h[et[e]], 1);
    __syncthreads();
    for (int i = threadIdx.x; i < RNUM; i += blockDim.x)
        g_bh[blockIdx.x * RNUM + i] = h[i];
}

// Single block: per-relation scan over block hists, tile list, global offsets.
__global__ void k_offsets() {
    __shared__ int relStart[RNUM];
    int r = threadIdx.x;
    if (r < RNUM) {
        int running = 0;
        for (int blk = 0; blk < SBLOCKS; blk++) {
            g_bo[blk * RNUM + r] = running;
            running += g_bh[blk * RNUM + r];
        }
        g_hist[r] = running;   // per-relation count
    }
    __syncthreads();
    if (threadIdx.x == 0) {
        int running = 0, n = 0;
        for (int rr = 0; rr < RNUM; rr++) {
            relStart[rr] = running;
            int c = g_hist[rr];
            int t = 0;
            while (t < c) {
                int len = (c - t < TE) ? (c - t) : TE;
                g_tiles[n] = make_int4(rr, running + t, len, 0);
                n++;
                t += TE;
            }
            running += c;
        }
        g_numTiles = n;
    }
    __syncthreads();
    if (r < RNUM) {
        int rs = relStart[r];
        for (int blk = 0; blk < SBLOCKS; blk++)
            g_bo[blk * RNUM + r] += rs;
    }
}

__global__ void k_scatter(const int* __restrict__ src, const int* __restrict__ dst,
                          const int* __restrict__ et, const float* __restrict__ norm, int E) {
    __shared__ int cur[RNUM];
    for (int i = threadIdx.x; i < RNUM; i += blockDim.x)
        cur[i] = g_bo[blockIdx.x * RNUM + i];
    __syncthreads();
    int chunk = (E + SBLOCKS - 1) / SBLOCKS;
    int lo = blockIdx.x * chunk;
    int hi = min(E, lo + chunk);
    for (int e = lo + threadIdx.x; e < hi; e += blockDim.x) {
        int r = et[e];
        int p = atomicAdd(&cur[r], 1);
        g_edges[p] = make_int4(src[e], dst[e], __float_as_int(norm[e]), 0);
    }
}

// ---------------- weight packing ----------------
// Layer 64->64: row-PAIR packed: float idx = r*4096 + kp*128 + c*2 + rr
// i.e. float2 entry [kp*64 + c] = { W[2kp][c], W[2kp+1][c] }  (k-vectorized fma2)
__global__ void k_packW64(const float* __restrict__ coeff, const float* __restrict__ bases) {
    int idx = blockIdx.x * blockDim.x + threadIdx.x;
    if (idx >= RNUM * 4096) return;
    int r   = idx >> 12;
    int rem = idx & 4095;
    int kp  = rem >> 7;
    int c   = (rem >> 1) & 63;
    int rr  = rem & 1;
    int row = 2 * kp + rr;
    float v = 0.f;
#pragma unroll
    for (int b = 0; b < BNUM; b++)
        v += coeff[r * BNUM + b] * bases[(b * HDIM + row) * HDIM + c];
    g_Wp[idx] = v;
}

// Layer 64->16: float layout idx = r*1024 + rp*32 + j*2 + rr
// entry(8B) [rp*16+j] = { W[2rp][j], W[2rp+1][j] }
__global__ void k_packW16(const float* __restrict__ coeff, const float* __restrict__ bases) {
    int idx = blockIdx.x * blockDim.x + threadIdx.x;
    if (idx >= RNUM * 1024) return;
    int r   = idx >> 10;
    int rem = idx & 1023;
    int rp  = rem >> 5;
    int j   = (rem >> 1) & 15;
    int rr  = rem & 1;
    int row = 2 * rp + rr;
    float v = 0.f;
#pragma unroll
    for (int b = 0; b < BNUM; b++)
        v += coeff[r * BNUM + b] * bases[(b * HDIM + row) * ODIM + j];
    g_Wp[idx] = v;
}

__global__ void k_init(float* __restrict__ h, const float* __restrict__ bias,
                       int total, int mask) {
    int i = blockIdx.x * blockDim.x + threadIdx.x;
    if (i < total) h[i] = bias[i & mask];
}

// ---------------- edge kernel, 64 output cols ----------------
// Block: 4 warps, one tile (<=512 edges, single relation). W_r staged in smem
// (row-pair packed). Warp pass: 16 edges; lane = half*16 + cq; half-warp h
// handles edges 8h..8h+7, lane owns output cols 4cq..4cq+3. Accumulators are
// k-vectorized f32x2 ({even-k, odd-k} partials), folded at the end. X staged
// as raw pairs with an XOR bank swizzle so the two halves' concurrent loads
// never conflict.
template <bool RELU>
__global__ void __launch_bounds__(EWARPS * 32)
k_edge64(const float* __restrict__ x, float* __restrict__ hout) {
    __shared__ ulonglong2 sW[1024];                        // 16 KB: [kp*32 + 2c..]
    __shared__ unsigned long long sX[EWARPS][EB64][32];    // 16 KB raw x pairs

    int tb = blockIdx.x;
    if (tb >= g_numTiles) return;
    int4 tile = g_tiles[tb];
    int rel = tile.x, start = tile.y, len = tile.z;

    {   // stage packed W_r (16 KB) into smem
        const float4* wg = (const float4*)(g_Wp + (size_t)rel * 4096);
        float4* ws = (float4*)sW;
        for (int i = threadIdx.x; i < 1024; i += blockDim.x) ws[i] = wg[i];
    }
    __syncthreads();

    const int warp = threadIdx.x >> 5;
    const int lane = threadIdx.x & 31;
    const int half = lane >> 4;
    const int cq   = lane & 15;
    const float2* x2 = (const float2*)x;

    for (int base = warp * EB64; base < len; base += EWARPS * EB64) {
        __syncwarp();
        int cnt = min(EB64, len - base);
        int4 md = make_int4(0, 0, 0, 0);
        if (lane < cnt) md = g_edges[start + base + lane];

        // stage x rows as raw pairs (norm-prescaled, relu'd), bank-swizzled
#pragma unroll
        for (int e = 0; e < EB64; e++) {
            int   ss = __shfl_sync(FULLMASK, md.x, e);
            float nn = __int_as_float(__shfl_sync(FULLMASK, md.z, e));
            float2 v = x2[(size_t)ss * 32 + lane];
            if (RELU) { v.x = fmaxf(v.x, 0.f); v.y = fmaxf(v.y, 0.f); }
            v.x *= nn; v.y *= nn;
            sX[warp][e][lane ^ ((e >> 3) & 1)] = pack2(v.x, v.y);
        }
        __syncwarp();

        unsigned long long acc[8][4];
#pragma unroll
        for (int e = 0; e < 8; e++)
#pragma unroll
            for (int c = 0; c < 4; c++) acc[e][c] = 0ull;

#pragma unroll 4
        for (int kp = 0; kp < 32; kp++) {
            ulonglong2 wa = sW[kp * 32 + 2 * cq];      // cols 4cq, 4cq+1 (row-pairs)
            ulonglong2 wb = sW[kp * 32 + 2 * cq + 1];  // cols 4cq+2, 4cq+3
#pragma unroll
            for (int e = 0; e < 8; e++) {
                unsigned long long xp = sX[warp][half * 8 + e][kp ^ half];
                acc[e][0] = fma2(xp, wa.x, acc[e][0]);
                acc[e][1] = fma2(xp, wa.y, acc[e][1]);
                acc[e][2] = fma2(xp, wb.x, acc[e][2]);
                acc[e][3] = fma2(xp, wb.y, acc[e][3]);
            }
        }

#pragma unroll
        for (int e = 0; e < 8; e++) {
            int eg = half * 8 + e;
            int d  = __shfl_sync(FULLMASK, md.y, eg);
            if (eg < cnt) {
                atomicAdd((float4*)(hout + (size_t)d * 64 + cq * 4),
                          make_float4(fold2(acc[e][0]), fold2(acc[e][1]),
                                      fold2(acc[e][2]), fold2(acc[e][3])));
            }
        }
    }
}

// ---------------- edge kernel, 16 output cols (final layer) ----------------
// lane = half*16 + j : half splits the i-range (i in [32h, 32h+32)), lane owns col j.
__device__ __forceinline__ int swz16(int l) { return l ^ ((l >> 4) & 1); }

__global__ void __launch_bounds__(EWARPS * 32)
k_edge16(const float* __restrict__ x, float* __restrict__ out) {
    __shared__ unsigned long long sW2[32 * 16];            // 4 KB
    __shared__ unsigned long long sX2[EWARPS][EBATCH][32]; // 8 KB (raw pairs, swizzled)

    int tb = blockIdx.x;
    if (tb >= g_numTiles) return;
    int4 tile = g_tiles[tb];
    int rel = tile.x, start = tile.y, len = tile.z;

    {
        const unsigned long long* wg = (const unsigned long long*)(g_Wp + (size_t)rel * 1024);
        for (int i = threadIdx.x; i < 512; i += blockDim.x) sW2[i] = wg[i];
    }
    __syncthreads();

    const int warp = threadIdx.x >> 5;
    const int lane = threadIdx.x & 31;
    const int half = lane >> 4;
    const int j    = lane & 15;
    const float2* x2 = (const float2*)x;

    // hoist this lane's W column pairs into registers (shared across all edges)
    unsigned long long wr[16];
#pragma unroll
    for (int t = 0; t < 16; t++) wr[t] = sW2[(half * 16 + t) * 16 + j];

    for (int base = warp * EBATCH; base < len; base += EWARPS * EBATCH) {
        __syncwarp();
        int4 ed = make_int4(0, 0, 0, 0);
        if (lane < EBATCH && base + lane < len)
            ed = g_edges[start + base + lane];
        int s = ed.x, d = ed.y;
        float nm = __int_as_float(ed.z);

#pragma unroll
        for (int e = 0; e < EBATCH; e++) {
            int   ss = __shfl_sync(FULLMASK, s, e);
            float nn = __shfl_sync(FULLMASK, nm, e);
            float2 v = x2[(size_t)ss * 32 + lane];
            v.x = fmaxf(v.x, 0.f); v.y = fmaxf(v.y, 0.f);   // final layer always relu's input
            v.x *= nn; v.y *= nn;
            sX2[warp][e][swz16(lane)] = pack2(v.x, v.y);
        }
        __syncwarp();

#pragma unroll
        for (int e = 0; e < EBATCH; e++) {
            unsigned long long acc = 0ull;
#pragma unroll
            for (int t = 0; t < 16; t++)
                acc = fma2(sX2[warp][e][swz16(half * 16 + t)], wr[t], acc);
            float rs = fold2(acc);
            rs += __shfl_xor_sync(FULLMASK, rs, 16);      // combine the two i-halves
            float v1 = __shfl_down_sync(FULLMASK, rs, 1);
            float v2 = __shfl_down_sync(FULLMASK, rs, 2);
            float v3 = __shfl_down_sync(FULLMASK, rs, 3);
            int de = __shfl_sync(FULLMASK, d, e);
            if (half == 0 && (j & 3) == 0)
                atomicAdd((float4*)(out + (size_t)de * 16 + j),
                          make_float4(rs, v1, v2, v3));
        }
    }
}

// ---------------- launch ----------------
extern "C" void kernel_launch(void* const* d_in, const int* in_sizes, int n_in,
                              void* d_out, int out_size) {
    const float* feats  = (const float*)d_in[0];
    const float* coeff0 = (const float*)d_in[1];
    const float* bases0 = (const float*)d_in[2];
    const float* bias0  = (const float*)d_in[3];
    const float* coeff1 = (const float*)d_in[4];
    const float* bases1 = (const float*)d_in[5];
    const float* bias1  = (const float*)d_in[6];
    const float* coeff2 = (const float*)d_in[7];
    const float* bases2 = (const float*)d_in[8];
    const float* bias2  = (const float*)d_in[9];
    const int*   src    = (const int*)d_in[10];
    const int*   dst    = (const int*)d_in[11];
    const int*   etype  = (const int*)d_in[12];
    const float* norm   = (const float*)d_in[13];
    float* out = (float*)d_out;

    int E = in_sizes[10];
    if (E > NEDGES) E = NEDGES;
    int N = in_sizes[0] / HDIM;
    if (N > NNODES) N = NNODES;

    float* h0;  cudaGetSymbolAddress((void**)&h0, g_h0);
    float* h1;  cudaGetSymbolAddress((void**)&h1, g_h1);

    // ---- sort edges by relation (shared by all 3 layers) ----
    k_hist<<<SBLOCKS, 256>>>(etype, E);
    k_offsets<<<1, 128>>>();
    k_scatter<<<SBLOCKS, 256>>>(src, dst, etype, norm, E);

    int gridTiles = MAX_TILES;

    // ---- layer 0: feats -> h0 (relu applied by next layer's reader) ----
    k_packW64<<<(RNUM * 4096 + 255) / 256, 256>>>(coeff0, bases0);
    k_init<<<(N * HDIM + 255) / 256, 256>>>(h0, bias0, N * HDIM, HDIM - 1);
    k_edge64<false><<<gridTiles, EWARPS * 32>>>(feats, h0);

    // ---- layer 1: relu(h0) -> h1 ----
    k_packW64<<<(RNUM * 4096 + 255) / 256, 256>>>(coeff1, bases1);
    k_init<<<(N * HDIM + 255) / 256, 256>>>(h1, bias1, N * HDIM, HDIM - 1);
    k_edge64<true><<<gridTiles, EWARPS * 32>>>(h0, h1);

    // ---- layer 2: relu(h1) -> out ----
    k_packW16<<<(RNUM * 1024 + 255) / 256, 256>>>(coeff2, bases2);
    k_init<<<(N * ODIM + 255) / 256, 256>>>(out, bias2, N * ODIM, ODIM - 1);
    k_edge16<<<gridTiles, EWARPS * 32>>>(h1, out);
}

// round 9
// speedup vs baseline: 1.3402x; 1.0574x over previous
#include <cuda_runtime.h>
#include <cstdint>

#define FULLMASK 0xffffffffu

// Problem constants (fixed dataset)
constexpr int NNODES = 100000;
constexpr int NEDGES = 1000000;
constexpr int HDIM   = 64;
constexpr int ODIM   = 16;
constexpr int RNUM   = 90;
constexpr int BNUM   = 8;

constexpr int TE      = 512;   // edges per tile (one relation per tile)
constexpr int EWARPS  = 4;     // warps per edge-block
constexpr int EB64    = 16;    // edges per warp per pass (edge64 kernel)
constexpr int EBATCH  = 8;     // edges per warp per pass (edge16 kernel)
constexpr int SBLOCKS = 512;   // blocks for hist/scatter
constexpr int MAX_TILES = NEDGES / TE + RNUM + 8;

// prep-kernel block partition
constexpr int PK64_BLKS = RNUM * 4096 / 256;   // 1440 (per 64->64 layer)
constexpr int PK16_BLKS = RNUM * 1024 / 256;   // 360
constexpr int IH_BLKS   = NNODES * HDIM / 4 / 256;          // 6250 (per h buffer)
constexpr int IO_BLKS   = (NNODES * ODIM / 4 + 255) / 256;  // 1563
constexpr int B_PK1  = PK64_BLKS;
constexpr int B_PK2  = B_PK1 + PK64_BLKS;
constexpr int B_PK16 = B_PK2 + PK16_BLKS;
constexpr int B_I0   = B_PK16 + IH_BLKS;
constexpr int B_I1   = B_I0 + IH_BLKS;
constexpr int B_IO   = B_I1 + IO_BLKS;
constexpr int PREP_BLKS = B_IO + SBLOCKS;

// ---------------- scratch (device globals; no allocation) ----------------
__device__ float g_h0[(size_t)NNODES * HDIM];
__device__ float g_h1[(size_t)NNODES * HDIM];
__device__ float g_Wp0[RNUM * HDIM * HDIM];
__device__ float g_Wp1[RNUM * HDIM * HDIM];
__device__ float g_Wp2[RNUM * HDIM * ODIM];
__device__ int   g_hist[RNUM];
__device__ int   g_bh[SBLOCKS * RNUM];       // per-block relation histograms
__device__ int   g_bo[SBLOCKS * RNUM];       // per-block scatter offsets
__device__ int4  g_tiles[MAX_TILES];         // {rel, start, len, 0}
__device__ int   g_numTiles;
__device__ int4  g_edges[NEDGES];            // {src, dst, bits(norm), 0} sorted by relation

// ---------------- f32x2 helpers ----------------
__device__ __forceinline__ unsigned long long pack2(float lo, float hi) {
    unsigned long long r;
    asm("mov.b64 %0, {%1, %2};" : "=l"(r) : "f"(lo), "f"(hi));
    return r;
}
__device__ __forceinline__ float2 unpack2(unsigned long long v) {
    float2 f;
    asm("mov.b64 {%0, %1}, %2;" : "=f"(f.x), "=f"(f.y) : "l"(v));
    return f;
}
__device__ __forceinline__ unsigned long long fma2(unsigned long long a,
                                                   unsigned long long b,
                                                   unsigned long long c) {
    unsigned long long d;
    asm("fma.rn.f32x2 %0, %1, %2, %3;" : "=l"(d) : "l"(a), "l"(b), "l"(c));
    return d;
}
__device__ __forceinline__ float fold2(unsigned long long a) {
    float2 f = unpack2(a);
    return f.x + f.y;
}

// ---------------- fused prologue: pack W x3 + init x3 + histogram ----------
// Layer 64->64 pack: row-PAIR packed: float idx = r*4096 + kp*128 + c*2 + rr
//   float2 entry [kp*64 + c] = { W[2kp][c], W[2kp+1][c] }
// Layer 64->16 pack: entry(8B) [rp*16+j] = { W[2rp][j], W[2rp+1][j] }
__device__ __forceinline__ void pack64_body(int blk, const float* __restrict__ coeff,
                                            const float* __restrict__ bases,
                                            float* __restrict__ Wp) {
    int idx = blk * 256 + threadIdx.x;
    int r   = idx >> 12;
    int rem = idx & 4095;
    int kp  = rem >> 7;
    int c   = (rem >> 1) & 63;
    int rr  = rem & 1;
    int row = 2 * kp + rr;
    float v = 0.f;
#pragma unroll
    for (int b = 0; b < BNUM; b++)
        v += coeff[r * BNUM + b] * bases[(b * HDIM + row) * HDIM + c];
    Wp[idx] = v;
}

__global__ void __launch_bounds__(256)
k_prep(const float* __restrict__ coeff0, const float* __restrict__ bases0,
       const float* __restrict__ bias0,
       const float* __restrict__ coeff1, const float* __restrict__ bases1,
       const float* __restrict__ bias1,
       const float* __restrict__ coeff2, const float* __restrict__ bases2,
       const float* __restrict__ bias2,
       const int* __restrict__ etype, int E,
       float* __restrict__ out) {
    int blk = blockIdx.x;
    if (blk < B_PK1) {
        pack64_body(blk, coeff0, bases0, g_Wp0);
    } else if (blk < B_PK2) {
        pack64_body(blk - B_PK1, coeff1, bases1, g_Wp1);
    } else if (blk < B_PK16) {
        int idx = (blk - B_PK2) * 256 + threadIdx.x;
        int r   = idx >> 10;
        int rem = idx & 1023;
        int rp  = rem >> 5;
        int j   = (rem >> 1) & 15;
        int rr  = rem & 1;
        int row = 2 * rp + rr;
        float v = 0.f;
#pragma unroll
        for (int b = 0; b < BNUM; b++)
            v += coeff2[r * BNUM + b] * bases2[(b * HDIM + row) * ODIM + j];
        g_Wp2[idx] = v;
    } else if (blk < B_I0) {
        int i = (blk - B_PK16) * 256 + threadIdx.x;          // float4 index
        ((float4*)g_h0)[i] = ((const float4*)bias0)[i & 15]; // 64/4 = 16 per row
    } else if (blk < B_I1) {
        int i = (blk - B_I0) * 256 + threadIdx.x;
        ((float4*)g_h1)[i] = ((const float4*)bias1)[i & 15];
    } else if (blk < B_IO) {
        int i = (blk - B_I1) * 256 + threadIdx.x;
        if (i < NNODES * ODIM / 4)
            ((float4*)out)[i] = ((const float4*)bias2)[i & 3];
    } else {
        // histogram block
        int hb = blk - B_IO;
        __shared__ int h[RNUM];
        for (int i = threadIdx.x; i < RNUM; i += 256) h[i] = 0;
        __syncthreads();
        int chunk = (E + SBLOCKS - 1) / SBLOCKS;
        int lo = hb * chunk;
        int hi = min(E, lo + chunk);
        for (int e = lo + threadIdx.x; e < hi; e += 256)
            atomicAdd(&h[etype[e]], 1);
        __syncthreads();
        for (int i = threadIdx.x; i < RNUM; i += 256)
            g_bh[hb * RNUM + i] = h[i];
    }
}

// ---------------- offsets: two-level scan + tile list (one block) ----------
constexpr int SEG = 8;
constexpr int BPS = SBLOCKS / SEG;  // 64

__global__ void __launch_bounds__(1024)
k_offsets() {
    __shared__ int part[RNUM][SEG];
    __shared__ int relStart[RNUM];
    int t = threadIdx.x;
    int r = t / SEG, s = t % SEG;
    if (t < RNUM * SEG) {
        int sum = 0;
#pragma unroll 4
        for (int b = s * BPS; b < (s + 1) * BPS; b++)
            sum += g_bh[b * RNUM + r];
        part[r][s] = sum;
    }
    __syncthreads();
    if (t < RNUM) {
        int run = 0;
#pragma unroll
        for (int ss = 0; ss < SEG; ss++) {
            int v = part[t][ss];
            part[t][ss] = run;
            run += v;
        }
        g_hist[t] = run;
    }
    __syncthreads();
    if (t == 0) {
        int running = 0, n = 0;
        for (int rr = 0; rr < RNUM; rr++) {
            relStart[rr] = running;
            int c = g_hist[rr];
            for (int off = 0; off < c; off += TE) {
                int len = (c - off < TE) ? (c - off) : TE;
                g_tiles[n++] = make_int4(rr, running + off, len, 0);
            }
            running += c;
        }
        g_numTiles = n;
    }
    __syncthreads();
    if (t < RNUM * SEG) {
        int run = relStart[r] + part[r][s];
        for (int b = s * BPS; b < (s + 1) * BPS; b++) {
            int v = g_bh[b * RNUM + r];
            g_bo[b * RNUM + r] = run;
            run += v;
        }
    }
}

__global__ void k_scatter(const int* __restrict__ src, const int* __restrict__ dst,
                          const int* __restrict__ et, const float* __restrict__ norm, int E) {
    __shared__ int cur[RNUM];
    for (int i = threadIdx.x; i < RNUM; i += blockDim.x)
        cur[i] = g_bo[blockIdx.x * RNUM + i];
    __syncthreads();
    int chunk = (E + SBLOCKS - 1) / SBLOCKS;
    int lo = blockIdx.x * chunk;
    int hi = min(E, lo + chunk);
    for (int e = lo + threadIdx.x; e < hi; e += blockDim.x) {
        int r = et[e];
        int p = atomicAdd(&cur[r], 1);
        g_edges[p] = make_int4(src[e], dst[e], __float_as_int(norm[e]), 0);
    }
}

// ---------------- edge kernel, 64 output cols ----------------
// Block: 4 warps, one tile (<=512 edges, single relation). W_r staged in smem
// (row-pair packed). Warp pass: 16 edges; lane = half*16 + cq; half-warp h
// handles edges 8h..8h+7, lane owns output cols 4cq..4cq+3. Accumulators are
// k-vectorized f32x2 ({even-k, odd-k} partials), folded at the end. X staged
// as raw pairs with an XOR bank swizzle; edge metadata broadcast via smem.
template <bool RELU>
__global__ void __launch_bounds__(EWARPS * 32)
k_edge64(const float* __restrict__ x, float* __restrict__ hout,
         const float* __restrict__ Wp) {
    __shared__ ulonglong2 sW[1024];                        // 16 KB: [kp*32 + 2c..]
    __shared__ unsigned long long sX[EWARPS][EB64][32];    // 16 KB raw x pairs
    __shared__ int2 sM[EWARPS][EB64];                      // (src, normbits)
    __shared__ int  sD[EWARPS][EB64];                      // dst

    int tb = blockIdx.x;
    if (tb >= g_numTiles) return;
    int4 tile = g_tiles[tb];
    int rel = tile.x, start = tile.y, len = tile.z;

    {   // stage packed W_r (16 KB) into smem
        const float4* wg = (const float4*)(Wp + (size_t)rel * 4096);
        float4* ws = (float4*)sW;
        for (int i = threadIdx.x; i < 1024; i += blockDim.x) ws[i] = wg[i];
    }
    __syncthreads();

    const int warp = threadIdx.x >> 5;
    const int lane = threadIdx.x & 31;
    const int half = lane >> 4;
    const int cq   = lane & 15;
    const float2* x2 = (const float2*)x;

    for (int base = warp * EB64; base < len; base += EWARPS * EB64) {
        __syncwarp();
        int cnt = min(EB64, len - base);
        if (lane < EB64) {
            int4 md = make_int4(0, 0, 0, 0);
            if (lane < cnt) md = g_edges[start + base + lane];
            sM[warp][lane] = make_int2(md.x, md.z);
            sD[warp][lane] = md.y;
        }
        __syncwarp();

        // stage x rows as raw pairs (norm-prescaled, relu'd), bank-swizzled
#pragma unroll
        for (int e = 0; e < EB64; e++) {
            int2 m = sM[warp][e];
            float nn = __int_as_float(m.y);
            float2 v = x2[(size_t)m.x * 32 + lane];
            if (RELU) { v.x = fmaxf(v.x, 0.f); v.y = fmaxf(v.y, 0.f); }
            v.x *= nn; v.y *= nn;
            sX[warp][e][lane ^ ((e >> 3) & 1)] = pack2(v.x, v.y);
        }
        __syncwarp();

        unsigned long long acc[8][4];
#pragma unroll
        for (int e = 0; e < 8; e++)
#pragma unroll
            for (int c = 0; c < 4; c++) acc[e][c] = 0ull;

#pragma unroll 4
        for (int kp = 0; kp < 32; kp++) {
            ulonglong2 wa = sW[kp * 32 + 2 * cq];      // cols 4cq, 4cq+1 (row-pairs)
            ulonglong2 wb = sW[kp * 32 + 2 * cq + 1];  // cols 4cq+2, 4cq+3
#pragma unroll
            for (int e = 0; e < 8; e++) {
                unsigned long long xp = sX[warp][half * 8 + e][kp ^ half];
                acc[e][0] = fma2(xp, wa.x, acc[e][0]);
                acc[e][1] = fma2(xp, wa.y, acc[e][1]);
                acc[e][2] = fma2(xp, wb.x, acc[e][2]);
                acc[e][3] = fma2(xp, wb.y, acc[e][3]);
            }
        }

#pragma unroll
        for (int e = 0; e < 8; e++) {
            int eg = half * 8 + e;
            if (eg < cnt) {
                int d = sD[warp][eg];
                atomicAdd((float4*)(hout + (size_t)d * 64 + cq * 4),
                          make_float4(fold2(acc[e][0]), fold2(acc[e][1]),
                                      fold2(acc[e][2]), fold2(acc[e][3])));
            }
        }
    }
}

// ---------------- edge kernel, 16 output cols (final layer) ----------------
// lane = half*16 + j : half splits the i-range (i in [32h, 32h+32)), lane owns col j.
__device__ __forceinline__ int swz16(int l) { return l ^ ((l >> 4) & 1); }

__global__ void __launch_bounds__(EWARPS * 32)
k_edge16(const float* __restrict__ x, float* __restrict__ out) {
    __shared__ unsigned long long sW2[32 * 16];            // 4 KB
    __shared__ unsigned long long sX2[EWARPS][EBATCH][32]; // 8 KB (raw pairs, swizzled)
    __shared__ int2 sM[EWARPS][EBATCH];
    __shared__ int  sD[EWARPS][EBATCH];

    int tb = blockIdx.x;
    if (tb >= g_numTiles) return;
    int4 tile = g_tiles[tb];
    int rel = tile.x, start = tile.y, len = tile.z;

    {
        const unsigned long long* wg = (const unsigned long long*)(g_Wp2 + (size_t)rel * 1024);
        for (int i = threadIdx.x; i < 512; i += blockDim.x) sW2[i] = wg[i];
    }
    __syncthreads();

    const int warp = threadIdx.x >> 5;
    const int lane = threadIdx.x & 31;
    const int half = lane >> 4;
    const int j    = lane & 15;
    const float2* x2 = (const float2*)x;

    // hoist this lane's W column pairs into registers (shared across all edges)
    unsigned long long wr[16];
#pragma unroll
    for (int t = 0; t < 16; t++) wr[t] = sW2[(half * 16 + t) * 16 + j];

    for (int base = warp * EBATCH; base < len; base += EWARPS * EBATCH) {
        __syncwarp();
        int cnt = min(EBATCH, len - base);
        if (lane < EBATCH) {
            int4 ed = make_int4(0, 0, 0, 0);
            if (lane < cnt) ed = g_edges[start + base + lane];
            sM[warp][lane] = make_int2(ed.x, ed.z);
            sD[warp][lane] = ed.y;
        }
        __syncwarp();

#pragma unroll
        for (int e = 0; e < EBATCH; e++) {
            int2 m = sM[warp][e];
            float nn = __int_as_float(m.y);
            float2 v = x2[(size_t)m.x * 32 + lane];
            v.x = fmaxf(v.x, 0.f); v.y = fmaxf(v.y, 0.f);   // final layer always relu's input
            v.x *= nn; v.y *= nn;
            sX2[warp][e][swz16(lane)] = pack2(v.x, v.y);
        }
        __syncwarp();

#pragma unroll
        for (int e = 0; e < EBATCH; e++) {
            unsigned long long acc = 0ull;
#pragma unroll
            for (int t = 0; t < 16; t++)
                acc = fma2(sX2[warp][e][swz16(half * 16 + t)], wr[t], acc);
            float rs = fold2(acc);
            rs += __shfl_xor_sync(FULLMASK, rs, 16);      // combine the two i-halves
            float v1 = __shfl_down_sync(FULLMASK, rs, 1);
            float v2 = __shfl_down_sync(FULLMASK, rs, 2);
            float v3 = __shfl_down_sync(FULLMASK, rs, 3);
            if (e < cnt && half == 0 && (j & 3) == 0) {
                int de = sD[warp][e];
                atomicAdd((float4*)(out + (size_t)de * 16 + j),
                          make_float4(rs, v1, v2, v3));
            }
        }
    }
}

// ---------------- launch ----------------
extern "C" void kernel_launch(void* const* d_in, const int* in_sizes, int n_in,
                              void* d_out, int out_size) {
    const float* feats  = (const float*)d_in[0];
    const float* coeff0 = (const float*)d_in[1];
    const float* bases0 = (const float*)d_in[2];
    const float* bias0  = (const float*)d_in[3];
    const float* coeff1 = (const float*)d_in[4];
    const float* bases1 = (const float*)d_in[5];
    const float* bias1  = (const float*)d_in[6];
    const float* coeff2 = (const float*)d_in[7];
    const float* bases2 = (const float*)d_in[8];
    const float* bias2  = (const float*)d_in[9];
    const int*   src    = (const int*)d_in[10];
    const int*   dst    = (const int*)d_in[11];
    const int*   etype  = (const int*)d_in[12];
    const float* norm   = (const float*)d_in[13];
    float* out = (float*)d_out;

    int E = in_sizes[10];
    if (E > NEDGES) E = NEDGES;

    float* h0;  cudaGetSymbolAddress((void**)&h0, g_h0);
    float* h1;  cudaGetSymbolAddress((void**)&h1, g_h1);
    float* w0;  cudaGetSymbolAddress((void**)&w0, g_Wp0);
    float* w1;  cudaGetSymbolAddress((void**)&w1, g_Wp1);

    // ---- fused prologue: pack all W, init all outputs, histogram ----
    k_prep<<<PREP_BLKS, 256>>>(coeff0, bases0, bias0,
                               coeff1, bases1, bias1,
                               coeff2, bases2, bias2,
                               etype, E, out);
    k_offsets<<<1, 1024>>>();
    k_scatter<<<SBLOCKS, 256>>>(src, dst, etype, norm, E);

    int gridTiles = MAX_TILES;

    // ---- layer 0: feats -> h0 (relu applied by next layer's reader) ----
    k_edge64<false><<<gridTiles, EWARPS * 32>>>(feats, h0, w0);
    // ---- layer 1: relu(h0) -> h1 ----
    k_edge64<true><<<gridTiles, EWARPS * 32>>>(h0, h1, w1);
    // ---- layer 2: relu(h1) -> out ----
    k_edge16<<<gridTiles, EWARPS * 32>>>(h1, out);
}